// round 14
// baseline (speedup 1.0000x reference)
#include <cuda_runtime.h>
#include <math.h>

#define Bsz 4
#define Cch 192
#define Hh 56
#define Ww 56
#define HW (Hh*Ww)

// scratch (static device globals; no allocation)
__device__ float g_xt  [Bsz*HW*Cch];  // x transposed to [b][n][c]  (NHWC)
__device__ float g_att [Bsz*HW*Cch];  // attention output, h-shift part
__device__ float g_attw[Bsz*HW*Cch];  // attention output, w-shift part
__device__ float g_sc  [Bsz*HW*32];   // scores, padded row of 32
__device__ __align__(16) float g_acc[Cch*Bsz*HW];  // x-half GEMM partial [o][r]

// ---------------------------------------------------------------------------
// Kernel 1: NCHW -> NHWC transpose
// ---------------------------------------------------------------------------
__global__ __launch_bounds__(256) void transpose_k(const float* __restrict__ x)
{
    __shared__ float tile[32][33];
    const int n0 = blockIdx.x << 5;
    const int c0 = blockIdx.y << 5;
    const int b  = blockIdx.z;
    const int tx = threadIdx.x, ty = threadIdx.y;
    const float* xb = x + (size_t)b * Cch * HW;
#pragma unroll
    for (int i = 0; i < 4; i++)
        tile[ty + i*8][tx] = xb[(size_t)(c0 + ty + i*8) * HW + n0 + tx];
    __syncthreads();
    float* dst = g_xt + (size_t)b * HW * Cch;
#pragma unroll
    for (int i = 0; i < 4; i++)
        dst[(size_t)(n0 + ty + i*8) * Cch + c0 + tx] = tile[tx][ty + i*8];
}

// ---------------------------------------------------------------------------
// tanh: (1-e)/(1+e) = 2*rcp(1+e) - 1,  e = 2^(-2a*log2e).  6 instr / 2 MUFU.
// ---------------------------------------------------------------------------
__device__ __forceinline__ float fast_tanh(float p)
{
    float z = fabsf(p) * -2.885390082f;
    float e; asm("ex2.approx.f32 %0, %1;" : "=f"(e) : "f"(z));
    float d = 1.0f + e;
    float r; asm("rcp.approx.f32 %0, %1;" : "=f"(r) : "f"(d));
    float t = fmaf(2.0f, r, -1.0f);
    return copysignf(t, p);
}

// ---------------------------------------------------------------------------
// Kernel 2: ring pair-score kernel (unchanged)
// ---------------------------------------------------------------------------
#define TS_STRIDE 193

template<int LO, int HI, int MODE>
__device__ __forceinline__ void score_compute(const float* sxr, const float* xr,
                                              float* ts, int c)
{
    int p = 0;
#pragma unroll
    for (int i = 0; i < 14; i++)
#pragma unroll
        for (int j = (MODE ? i + 1 : i); j < 14; j++) {
            if (p >= LO && p < HI)
                ts[(p - LO)*TS_STRIDE + c] = fast_tanh(sxr[i] * xr[j]);
            p++;
        }
}

__device__ __forceinline__ void reduce_rows(const float* ts, float* redS,
                                            int c, int nrows, int base)
{
    if (c < nrows) {
        const float* row = ts + c*TS_STRIDE;
        float s0=0.f, s1=0.f, s2=0.f, s3=0.f;
#pragma unroll 8
        for (int cc = 0; cc < 192; cc += 4) {
            s0 += row[cc]; s1 += row[cc+1]; s2 += row[cc+2]; s3 += row[cc+3];
        }
        redS[base + c] = (s0 + s1) + (s2 + s3);
    }
}

__global__ __launch_bounds__(192) void score_k()
{
    __shared__ float ts[53 * TS_STRIDE];
    __shared__ float redS[105];
    const int x = blockIdx.x;
    const int r = blockIdx.y;
    const int b = blockIdx.z >> 1, mode = blockIdx.z & 1;
    const int c = threadIdx.x;
    const float* base = g_xt + (size_t)b * HW * Cch;

    float xr[14], sxr[14];
#pragma unroll
    for (int a = 0; a < 14; a++) {
        int n = mode ? (x*Ww + r + 4*a) : ((r + 4*a)*Ww + x);
        xr[a]  = base[n*Cch + c];
        sxr[a] = xr[a] * 0.19245008972987526f;
    }
    const int NP = mode ? 91 : 105;

    if (mode == 0) score_compute<0,53,0>(sxr, xr, ts, c);
    else           score_compute<0,53,1>(sxr, xr, ts, c);
    __syncthreads();
    reduce_rows(ts, redS, c, 53, 0);
    __syncthreads();
    if (mode == 0) score_compute<53,105,0>(sxr, xr, ts, c);
    else           score_compute<53,91,1>(sxr, xr, ts, c);
    __syncthreads();
    reduce_rows(ts, redS, c, NP - 53, 53);
    __syncthreads();

    float* scb = g_sc + (size_t)b * HW * 32;
    if (mode == 0) {
        for (int e = c; e < 196; e += 192) {
            int a = e / 14, k = e % 14;
            int j = a - k; if (j < 0) j += 14;
            int lo = min(a, j), hi = max(a, j);
            int id = lo*14 - (lo*(lo-1))/2 + (hi - lo);
            int n = (r + 4*a)*Ww + x;
            scb[n*32 + k] = redS[id];
        }
    } else {
        for (int e = c; e < 182; e += 192) {
            int a = e / 13, m = e % 13 + 1;
            int j = a - m; if (j < 0) j += 14;
            int lo = min(a, j), hi = max(a, j);
            int id = lo*13 - (lo*(lo-1))/2 + (hi - lo - 1);
            int n = x*Ww + r + 4*a;
            scb[n*32 + 13 + m] = redS[id];
        }
    }
}

// ---------------------------------------------------------------------------
// Kernel 3: ring weighted-sum (unchanged)
// ---------------------------------------------------------------------------
__global__ __launch_bounds__(192) void sum_k()
{
    __shared__ float wgt[14*14];
    const int x = blockIdx.x, r = blockIdx.y;
    const int b = blockIdx.z >> 1, mode = blockIdx.z & 1;
    const int c = threadIdx.x;
    const float* base = g_xt + (size_t)b * HW * Cch;
    float* attb = (mode ? g_attw : g_att) + (size_t)b * HW * Cch;
    const float* scb = g_sc + (size_t)b * HW * 32;

    if (c < 14) {
        int n = mode ? (x*Ww + r + 4*c) : ((r + 4*c)*Ww + x);
        const float* srow = scb + n*32;
        float s[27], mx = -1e30f;
#pragma unroll
        for (int k = 0; k < 27; k++) { s[k] = srow[k]; mx = fmaxf(mx, s[k]); }
        float tot = 0.f;
#pragma unroll
        for (int k = 0; k < 27; k++) { s[k] = __expf(s[k] - mx); tot += s[k]; }
        float inv = __fdividef(1.f, tot);
        if (mode == 0) {
#pragma unroll
            for (int k = 0; k < 14; k++) wgt[c*14 + k] = s[k] * inv;
        } else {
#pragma unroll
            for (int m = 1; m < 14; m++) wgt[c*14 + m-1] = s[13 + m] * inv;
        }
    }
    __syncthreads();

    float xr[14];
#pragma unroll
    for (int a = 0; a < 14; a++) {
        int n = mode ? (x*Ww + r + 4*a) : ((r + 4*a)*Ww + x);
        xr[a] = base[n*Cch + c];
    }
#pragma unroll
    for (int a = 0; a < 14; a++) {
        int n = mode ? (x*Ww + r + 4*a) : ((r + 4*a)*Ww + x);
        float o = 0.f;
        if (mode == 0) {
#pragma unroll
            for (int k = 0; k < 14; k++) {
                int j = (a - k + 14) % 14;
                o = fmaf(wgt[a*14 + k], xr[j], o);
            }
        } else {
#pragma unroll
            for (int m = 1; m < 14; m++) {
                int j = (a - m + 14) % 14;
                o = fmaf(wgt[a*14 + m-1], xr[j], o);
            }
        }
        attb[n*Cch + c] = o;
    }
}

// ---------------------------------------------------------------------------
// GEMM halves.
// gemm_x: R11-geometry (8o x 4n tile, 128 regs, launch_bounds(256,2),
//   grid 98x3 = 294 short blocks) so it CO-RESIDES with score_k blocks
//   while overlapped.  acc = x . W[:, 0:192] -> g_acc raw fp32.
// gemm_att: R7-geometry 8x8 half (runs alone after join).
//   out = GELU(BN(g_acc + att . W[:, 192:384] + bias)).
// ---------------------------------------------------------------------------
#define GBK 32
#define WSTR 68
#define KSTR 33

#define FFMA2(d, a, b) asm("fma.rn.f32x2 %0, %1, %2, %0;" : "+l"(d) : "l"(a), "l"(b))
#define LDSDUP(bb, addr)                                                      \
    asm volatile("{\n\t.reg .f32 t;\n\tld.shared.f32 t, [%1];\n\t"            \
                 "mov.b64 %0, {t, t};\n\t}" : "=l"(bb) : "r"(addr))

__global__ __launch_bounds__(256, 2) void gemm_x(const float* __restrict__ cw)
{
    __shared__ __align__(16) float wS[GBK * WSTR];    // [k][o]  8.7KB
    __shared__ __align__(16) float catS[128 * KSTR];  // [n][k]  16.9KB
    const int t = threadIdx.x, lane = t & 31, wrp = t >> 5;
    const int ow = wrp & 1, nw = wrp >> 1;   // 2 o-warps x 4 n-warps
    const int ti = lane & 3, tj = lane >> 2; // 4 o-groups x 8 n-groups
    const int r0 = blockIdx.x * 128;
    const int o0 = blockIdx.y * 64;

    unsigned long long acc[4][4];
#pragma unroll
    for (int p = 0; p < 4; p++)
#pragma unroll
        for (int nn = 0; nn < 4; nn++) acc[p][nn] = 0ULL;

    const int kq = t & 7, rowb = t >> 3;

    unsigned cb0 = (unsigned)__cvta_generic_to_shared(catS);
    unsigned cadr[4];
#pragma unroll
    for (int i = 0; i < 4; i++)
        cadr[i] = cb0 + (unsigned)((nw*32 + tj*4 + i) * KSTR * 4);

    float4 cv[4], wv[2];
#define LOADX(KC) do {                                                        \
        _Pragma("unroll")                                                     \
        for (int s = 0; s < 4; s++)                                           \
            cv[s] = *reinterpret_cast<const float4*>(                         \
                &g_xt[(size_t)(r0 + rowb + 32*s)*Cch + (KC) + kq*4]);         \
        _Pragma("unroll")                                                     \
        for (int s = 0; s < 2; s++)                                           \
            wv[s] = *reinterpret_cast<const float4*>(                         \
                &cw[(o0 + rowb + 32*s)*384 + (KC) + kq*4]);                   \
    } while (0)

    LOADX(0);
#pragma unroll 1
    for (int it = 0; it < 6; it++) {
        __syncthreads();
#pragma unroll
        for (int s = 0; s < 4; s++) {
            const float* cp = &cv[s].x;
#pragma unroll
            for (int j = 0; j < 4; j++)
                catS[(rowb + 32*s)*KSTR + kq*4 + j] = cp[j];
        }
#pragma unroll
        for (int s = 0; s < 2; s++) {
            const float* wp = &wv[s].x;
#pragma unroll
            for (int j = 0; j < 4; j++)
                wS[(kq*4 + j)*WSTR + rowb + 32*s] = wp[j];
        }
        __syncthreads();
        if (it < 5) LOADX((it + 1) * GBK);
#pragma unroll 16
        for (int k = 0; k < GBK; k++) {
            ulonglong2 A0 = *reinterpret_cast<const ulonglong2*>(
                                &wS[k*WSTR + ow*32 + ti*8]);
            ulonglong2 A1 = *reinterpret_cast<const ulonglong2*>(
                                &wS[k*WSTR + ow*32 + ti*8 + 4]);
            unsigned long long a[4] = {A0.x, A0.y, A1.x, A1.y};
            unsigned long long bb[4];
#pragma unroll
            for (int i = 0; i < 4; i++)
                LDSDUP(bb[i], cadr[i] + (unsigned)(4*k));
#pragma unroll
            for (int p = 0; p < 4; p++)
#pragma unroll
                for (int nn = 0; nn < 4; nn++)
                    FFMA2(acc[p][nn], a[p], bb[nn]);
        }
    }

    // store raw partials: g_acc[o][global_r], float4 over 4 consecutive r
    const int rr = r0 + nw*32 + tj*4;
#pragma unroll
    for (int p = 0; p < 4; p++) {
#pragma unroll
        for (int q = 0; q < 2; q++) {
            const int o = o0 + ow*32 + ti*8 + 2*p + q;
            float4 rv; float* rp = &rv.x;
#pragma unroll
            for (int nn = 0; nn < 4; nn++) {
                unsigned long long v = acc[p][nn];
                rp[nn] = q ? __uint_as_float((unsigned)(v >> 32))
                           : __uint_as_float((unsigned)v);
            }
            *reinterpret_cast<float4*>(&g_acc[(size_t)o*(Bsz*HW) + rr]) = rv;
        }
    }
}

__global__ __launch_bounds__(256, 1) void gemm_att(
    const float* __restrict__ cw,
    const float* __restrict__ bias,
    const float* __restrict__ gamma,
    const float* __restrict__ beta,
    const float* __restrict__ mean,
    const float* __restrict__ var,
    float* __restrict__ out)
{
    __shared__ __align__(16) float wS[GBK * WSTR];    // 8.7KB
    __shared__ __align__(16) float catS[256 * KSTR];  // 33.8KB
    const int t = threadIdx.x, lane = t & 31, wrp = t >> 5;
    const int ti = lane & 7, tjw = lane >> 3;
    const int r0 = blockIdx.x * 256, o0 = blockIdx.y * 64;

    unsigned long long acc[4][8];
#pragma unroll
    for (int p = 0; p < 4; p++)
#pragma unroll
        for (int nn = 0; nn < 8; nn++) acc[p][nn] = 0ULL;

    const int kq = t & 7, rowb = t >> 3;

    unsigned cb0 = (unsigned)__cvta_generic_to_shared(catS);
    unsigned cadr[8];
#pragma unroll
    for (int i = 0; i < 8; i++) {
        int n = wrp*32 + ((i < 4) ? (4*tjw + i) : (16 + 4*tjw + i - 4));
        cadr[i] = cb0 + (unsigned)(n * KSTR * 4);
    }

    float4 cv[8], wv[2];
#define LOADA(KC) do {                                                        \
        _Pragma("unroll")                                                     \
        for (int s = 0; s < 8; s++) {                                         \
            size_t ix = (size_t)(r0 + rowb + 32*s)*Cch + (KC) + kq*4;         \
            float4 h = *reinterpret_cast<const float4*>(&g_att[ix]);          \
            float4 w = *reinterpret_cast<const float4*>(&g_attw[ix]);         \
            cv[s] = make_float4(h.x+w.x, h.y+w.y, h.z+w.z, h.w+w.w);          \
        }                                                                     \
        _Pragma("unroll")                                                     \
        for (int s = 0; s < 2; s++)                                           \
            wv[s] = *reinterpret_cast<const float4*>(                         \
                &cw[(o0 + rowb + 32*s)*384 + 192 + (KC) + kq*4]);             \
    } while (0)

    LOADA(0);
#pragma unroll 1
    for (int it = 0; it < 6; it++) {
        __syncthreads();
#pragma unroll
        for (int s = 0; s < 8; s++) {
            const float* cp = &cv[s].x;
#pragma unroll
            for (int j = 0; j < 4; j++)
                catS[(rowb + 32*s)*KSTR + kq*4 + j] = cp[j];
        }
#pragma unroll
        for (int s = 0; s < 2; s++) {
            const float* wp = &wv[s].x;
#pragma unroll
            for (int j = 0; j < 4; j++)
                wS[(kq*4 + j)*WSTR + rowb + 32*s] = wp[j];
        }
        __syncthreads();
        if (it < 5) LOADA((it + 1) * GBK);
#pragma unroll 16
        for (int k = 0; k < GBK; k++) {
            ulonglong2 A0 = *reinterpret_cast<const ulonglong2*>(
                                &wS[k*WSTR + 4*ti]);
            ulonglong2 A1 = *reinterpret_cast<const ulonglong2*>(
                                &wS[k*WSTR + 32 + 4*ti]);
            unsigned long long a[4] = {A0.x, A0.y, A1.x, A1.y};
            unsigned long long bb[8];
#pragma unroll
            for (int i = 0; i < 8; i++)
                LDSDUP(bb[i], cadr[i] + (unsigned)(4*k));
#pragma unroll
            for (int p = 0; p < 4; p++)
#pragma unroll
                for (int nn = 0; nn < 8; nn++)
                    FFMA2(acc[p][nn], a[p], bb[nn]);
        }
    }

    // epilogue: + g_acc, bias + BN(eval) + exact GELU, STG.128
#pragma unroll
    for (int qd = 0; qd < 2; qd++) {
        const int rq = r0 + wrp*32 + qd*16 + 4*tjw;
        const int bq = rq / HW;              // quad never splits batch
        const int nq = rq - bq*HW;
#pragma unroll
        for (int p = 0; p < 4; p++) {
            const int ob = (p < 2) ? (4*ti + 2*p) : (32 + 4*ti + 2*(p - 2));
#pragma unroll
            for (int q = 0; q < 2; q++) {
                const int o = o0 + ob + q;
                const float bi  = bias[o];
                const float inv = gamma[o] * rsqrtf(var[o] + 1e-5f);
                const float mu  = mean[o], bt = beta[o];
                float4 av = *reinterpret_cast<const float4*>(
                                &g_acc[(size_t)o*(Bsz*HW) + rq]);
                const float* ap = &av.x;
                float4 rv; float* rp = &rv.x;
#pragma unroll
                for (int ii = 0; ii < 4; ii++) {
                    unsigned long long v = acc[p][qd*4 + ii];
                    float yv = q ? __uint_as_float((unsigned)(v >> 32))
                                 : __uint_as_float((unsigned)v);
                    float y = (yv + ap[ii] + bi - mu) * inv + bt;
                    rp[ii] = 0.5f * y * (1.0f + erff(y * 0.70710678118654752f));
                }
                *reinterpret_cast<float4*>(
                    &out[(size_t)(bq*Cch + o)*HW + nq]) = rv;
            }
        }
    }
}

// ---------------------------------------------------------------------------
extern "C" void kernel_launch(void* const* d_in, const int* in_sizes, int n_in,
                              void* d_out, int out_size)
{
    const float* x     = (const float*)d_in[0];
    const float* cw    = (const float*)d_in[1];
    const float* cb    = (const float*)d_in[2];
    const float* gamma = (const float*)d_in[3];
    const float* beta  = (const float*)d_in[4];
    const float* mean  = (const float*)d_in[5];
    const float* var   = (const float*)d_in[6];
    float* out = (float*)d_out;

    static cudaStream_t s2 = nullptr, s3 = nullptr;
    static cudaEvent_t evA = nullptr, evB = nullptr, evC = nullptr;
    if (!s2) {
        cudaStreamCreateWithFlags(&s2, cudaStreamNonBlocking);
        cudaStreamCreateWithFlags(&s3, cudaStreamNonBlocking);
        cudaEventCreateWithFlags(&evA, cudaEventDisableTiming);
        cudaEventCreateWithFlags(&evB, cudaEventDisableTiming);
        cudaEventCreateWithFlags(&evC, cudaEventDisableTiming);
    }

    transpose_k<<<dim3(HW/32, Cch/32, Bsz), dim3(32, 8)>>>(x);

    // fork: both branches on non-default streams so they co-schedule
    cudaEventRecord(evA, 0);
    cudaStreamWaitEvent(s2, evA, 0);
    cudaStreamWaitEvent(s3, evA, 0);

    gemm_x<<<dim3(98, 3), 256, 0, s2>>>(cw);           // co-resident w/ score

    score_k<<<dim3(56, 4, 2*Bsz), 192, 0, s3>>>();
    sum_k<<<dim3(56, 4, 2*Bsz), 192, 0, s3>>>();

    // join, then att-half GEMM + epilogue
    cudaEventRecord(evB, s2);
    cudaEventRecord(evC, s3);
    cudaStreamWaitEvent(0, evB, 0);
    cudaStreamWaitEvent(0, evC, 0);
    gemm_att<<<dim3(49, 3), 256>>>(cw, cb, gamma, beta, mean, var, out);
}

// round 15
// speedup vs baseline: 1.0412x; 1.0412x over previous
#include <cuda_runtime.h>
#include <math.h>

#define Bsz 4
#define Cch 192
#define Hh 56
#define Ww 56
#define HW (Hh*Ww)

// scratch (static device globals; no allocation)
__device__ float g_xt  [Bsz*HW*Cch];  // x transposed to [b][n][c]  (NHWC)
__device__ float g_att [Bsz*HW*Cch];  // attention output, h-shift part
__device__ float g_attw[Bsz*HW*Cch];  // attention output, w-shift part
__device__ float g_sc  [Bsz*HW*32];   // scores, padded row of 32
__device__ __align__(16) float g_acc[Cch*Bsz*HW];  // x-half GEMM partial [o][r]

// ---------------------------------------------------------------------------
// Kernel 1: NCHW -> NHWC transpose
// ---------------------------------------------------------------------------
__global__ __launch_bounds__(256) void transpose_k(const float* __restrict__ x)
{
    __shared__ float tile[32][33];
    const int n0 = blockIdx.x << 5;
    const int c0 = blockIdx.y << 5;
    const int b  = blockIdx.z;
    const int tx = threadIdx.x, ty = threadIdx.y;
    const float* xb = x + (size_t)b * Cch * HW;
#pragma unroll
    for (int i = 0; i < 4; i++)
        tile[ty + i*8][tx] = xb[(size_t)(c0 + ty + i*8) * HW + n0 + tx];
    __syncthreads();
    float* dst = g_xt + (size_t)b * HW * Cch;
#pragma unroll
    for (int i = 0; i < 4; i++)
        dst[(size_t)(n0 + ty + i*8) * Cch + c0 + tx] = tile[tx][ty + i*8];
}

// ---------------------------------------------------------------------------
// tanh: (1-e)/(1+e) = 2*rcp(1+e) - 1,  e = 2^(-2a*log2e).  6 instr / 2 MUFU.
// ---------------------------------------------------------------------------
__device__ __forceinline__ float fast_tanh(float p)
{
    float z = fabsf(p) * -2.885390082f;
    float e; asm("ex2.approx.f32 %0, %1;" : "=f"(e) : "f"(z));
    float d = 1.0f + e;
    float r; asm("rcp.approx.f32 %0, %1;" : "=f"(r) : "f"(d));
    float t = fmaf(2.0f, r, -1.0f);
    return copysignf(t, p);
}

// ---------------------------------------------------------------------------
// Kernel 2: ring pair-score kernel (unchanged)
// ---------------------------------------------------------------------------
#define TS_STRIDE 193

template<int LO, int HI, int MODE>
__device__ __forceinline__ void score_compute(const float* sxr, const float* xr,
                                              float* ts, int c)
{
    int p = 0;
#pragma unroll
    for (int i = 0; i < 14; i++)
#pragma unroll
        for (int j = (MODE ? i + 1 : i); j < 14; j++) {
            if (p >= LO && p < HI)
                ts[(p - LO)*TS_STRIDE + c] = fast_tanh(sxr[i] * xr[j]);
            p++;
        }
}

__device__ __forceinline__ void reduce_rows(const float* ts, float* redS,
                                            int c, int nrows, int base)
{
    if (c < nrows) {
        const float* row = ts + c*TS_STRIDE;
        float s0=0.f, s1=0.f, s2=0.f, s3=0.f;
#pragma unroll 8
        for (int cc = 0; cc < 192; cc += 4) {
            s0 += row[cc]; s1 += row[cc+1]; s2 += row[cc+2]; s3 += row[cc+3];
        }
        redS[base + c] = (s0 + s1) + (s2 + s3);
    }
}

__global__ __launch_bounds__(192) void score_k()
{
    __shared__ float ts[53 * TS_STRIDE];
    __shared__ float redS[105];
    const int x = blockIdx.x;
    const int r = blockIdx.y;
    const int b = blockIdx.z >> 1, mode = blockIdx.z & 1;
    const int c = threadIdx.x;
    const float* base = g_xt + (size_t)b * HW * Cch;

    float xr[14], sxr[14];
#pragma unroll
    for (int a = 0; a < 14; a++) {
        int n = mode ? (x*Ww + r + 4*a) : ((r + 4*a)*Ww + x);
        xr[a]  = base[n*Cch + c];
        sxr[a] = xr[a] * 0.19245008972987526f;
    }
    const int NP = mode ? 91 : 105;

    if (mode == 0) score_compute<0,53,0>(sxr, xr, ts, c);
    else           score_compute<0,53,1>(sxr, xr, ts, c);
    __syncthreads();
    reduce_rows(ts, redS, c, 53, 0);
    __syncthreads();
    if (mode == 0) score_compute<53,105,0>(sxr, xr, ts, c);
    else           score_compute<53,91,1>(sxr, xr, ts, c);
    __syncthreads();
    reduce_rows(ts, redS, c, NP - 53, 53);
    __syncthreads();

    float* scb = g_sc + (size_t)b * HW * 32;
    if (mode == 0) {
        for (int e = c; e < 196; e += 192) {
            int a = e / 14, k = e % 14;
            int j = a - k; if (j < 0) j += 14;
            int lo = min(a, j), hi = max(a, j);
            int id = lo*14 - (lo*(lo-1))/2 + (hi - lo);
            int n = (r + 4*a)*Ww + x;
            scb[n*32 + k] = redS[id];
        }
    } else {
        for (int e = c; e < 182; e += 192) {
            int a = e / 13, m = e % 13 + 1;
            int j = a - m; if (j < 0) j += 14;
            int lo = min(a, j), hi = max(a, j);
            int id = lo*13 - (lo*(lo-1))/2 + (hi - lo - 1);
            int n = x*Ww + r + 4*a;
            scb[n*32 + 13 + m] = redS[id];
        }
    }
}

// ---------------------------------------------------------------------------
// Kernel 3: ring weighted-sum (unchanged)
// ---------------------------------------------------------------------------
__global__ __launch_bounds__(192) void sum_k()
{
    __shared__ float wgt[14*14];
    const int x = blockIdx.x, r = blockIdx.y;
    const int b = blockIdx.z >> 1, mode = blockIdx.z & 1;
    const int c = threadIdx.x;
    const float* base = g_xt + (size_t)b * HW * Cch;
    float* attb = (mode ? g_attw : g_att) + (size_t)b * HW * Cch;
    const float* scb = g_sc + (size_t)b * HW * 32;

    if (c < 14) {
        int n = mode ? (x*Ww + r + 4*c) : ((r + 4*c)*Ww + x);
        const float* srow = scb + n*32;
        float s[27], mx = -1e30f;
#pragma unroll
        for (int k = 0; k < 27; k++) { s[k] = srow[k]; mx = fmaxf(mx, s[k]); }
        float tot = 0.f;
#pragma unroll
        for (int k = 0; k < 27; k++) { s[k] = __expf(s[k] - mx); tot += s[k]; }
        float inv = __fdividef(1.f, tot);
        if (mode == 0) {
#pragma unroll
            for (int k = 0; k < 14; k++) wgt[c*14 + k] = s[k] * inv;
        } else {
#pragma unroll
            for (int m = 1; m < 14; m++) wgt[c*14 + m-1] = s[13 + m] * inv;
        }
    }
    __syncthreads();

    float xr[14];
#pragma unroll
    for (int a = 0; a < 14; a++) {
        int n = mode ? (x*Ww + r + 4*a) : ((r + 4*a)*Ww + x);
        xr[a] = base[n*Cch + c];
    }
#pragma unroll
    for (int a = 0; a < 14; a++) {
        int n = mode ? (x*Ww + r + 4*a) : ((r + 4*a)*Ww + x);
        float o = 0.f;
        if (mode == 0) {
#pragma unroll
            for (int k = 0; k < 14; k++) {
                int j = (a - k + 14) % 14;
                o = fmaf(wgt[a*14 + k], xr[j], o);
            }
        } else {
#pragma unroll
            for (int m = 1; m < 14; m++) {
                int j = (a - m + 14) % 14;
                o = fmaf(wgt[a*14 + m-1], xr[j], o);
            }
        }
        attb[n*Cch + c] = o;
    }
}

// ---------------------------------------------------------------------------
// GEMM halves.
// gemm_x: 8o x 4n tile, 128 regs, DYNAMIC smem padded to 120KB -> forced
//   1 block/SM, so 2 score_k blocks co-reside (regs 32.7+21.5K, smem
//   120+82KB all within SM budget). acc = x . W[:, 0:192] -> g_acc.
// gemm_att: 8x8 tile (runs alone after join):
//   out = GELU(BN(g_acc + att . W[:, 192:384] + bias)).
// ---------------------------------------------------------------------------
#define GBK 32
#define WSTR 68
#define KSTR 33
#define DSMB_X (120*1024)

#define FFMA2(d, a, b) asm("fma.rn.f32x2 %0, %1, %2, %0;" : "+l"(d) : "l"(a), "l"(b))
#define LDSDUP(bb, addr)                                                      \
    asm volatile("{\n\t.reg .f32 t;\n\tld.shared.f32 t, [%1];\n\t"            \
                 "mov.b64 %0, {t, t};\n\t}" : "=l"(bb) : "r"(addr))

__global__ __launch_bounds__(256, 1) void gemm_x(const float* __restrict__ cw)
{
    extern __shared__ __align__(16) float dsm[];
    float* wS   = dsm;                       // [k][o]  8.7KB
    float* catS = dsm + GBK*WSTR;            // [n][k]  16.9KB (rest dummy pad)
    const int t = threadIdx.x, lane = t & 31, wrp = t >> 5;
    const int ow = wrp & 1, nw = wrp >> 1;
    const int ti = lane & 3, tj = lane >> 2;
    const int r0 = blockIdx.x * 128;
    const int o0 = blockIdx.y * 64;

    unsigned long long acc[4][4];
#pragma unroll
    for (int p = 0; p < 4; p++)
#pragma unroll
        for (int nn = 0; nn < 4; nn++) acc[p][nn] = 0ULL;

    const int kq = t & 7, rowb = t >> 3;

    unsigned cb0 = (unsigned)__cvta_generic_to_shared(catS);
    unsigned cadr[4];
#pragma unroll
    for (int i = 0; i < 4; i++)
        cadr[i] = cb0 + (unsigned)((nw*32 + tj*4 + i) * KSTR * 4);

    float4 cv[4], wv[2];
#define LOADX(KC) do {                                                        \
        _Pragma("unroll")                                                     \
        for (int s = 0; s < 4; s++)                                           \
            cv[s] = *reinterpret_cast<const float4*>(                         \
                &g_xt[(size_t)(r0 + rowb + 32*s)*Cch + (KC) + kq*4]);         \
        _Pragma("unroll")                                                     \
        for (int s = 0; s < 2; s++)                                           \
            wv[s] = *reinterpret_cast<const float4*>(                         \
                &cw[(o0 + rowb + 32*s)*384 + (KC) + kq*4]);                   \
    } while (0)

    LOADX(0);
#pragma unroll 1
    for (int it = 0; it < 6; it++) {
        __syncthreads();
#pragma unroll
        for (int s = 0; s < 4; s++) {
            const float* cp = &cv[s].x;
#pragma unroll
            for (int j = 0; j < 4; j++)
                catS[(rowb + 32*s)*KSTR + kq*4 + j] = cp[j];
        }
#pragma unroll
        for (int s = 0; s < 2; s++) {
            const float* wp = &wv[s].x;
#pragma unroll
            for (int j = 0; j < 4; j++)
                wS[(kq*4 + j)*WSTR + rowb + 32*s] = wp[j];
        }
        __syncthreads();
        if (it < 5) LOADX((it + 1) * GBK);
#pragma unroll 16
        for (int k = 0; k < GBK; k++) {
            ulonglong2 A0 = *reinterpret_cast<const ulonglong2*>(
                                &wS[k*WSTR + ow*32 + ti*8]);
            ulonglong2 A1 = *reinterpret_cast<const ulonglong2*>(
                                &wS[k*WSTR + ow*32 + ti*8 + 4]);
            unsigned long long a[4] = {A0.x, A0.y, A1.x, A1.y};
            unsigned long long bb[4];
#pragma unroll
            for (int i = 0; i < 4; i++)
                LDSDUP(bb[i], cadr[i] + (unsigned)(4*k));
#pragma unroll
            for (int p = 0; p < 4; p++)
#pragma unroll
                for (int nn = 0; nn < 4; nn++)
                    FFMA2(acc[p][nn], a[p], bb[nn]);
        }
    }

    const int rr = r0 + nw*32 + tj*4;
#pragma unroll
    for (int p = 0; p < 4; p++) {
#pragma unroll
        for (int q = 0; q < 2; q++) {
            const int o = o0 + ow*32 + ti*8 + 2*p + q;
            float4 rv; float* rp = &rv.x;
#pragma unroll
            for (int nn = 0; nn < 4; nn++) {
                unsigned long long v = acc[p][nn];
                rp[nn] = q ? __uint_as_float((unsigned)(v >> 32))
                           : __uint_as_float((unsigned)v);
            }
            *reinterpret_cast<float4*>(&g_acc[(size_t)o*(Bsz*HW) + rr]) = rv;
        }
    }
}

__global__ __launch_bounds__(256, 1) void gemm_att(
    const float* __restrict__ cw,
    const float* __restrict__ bias,
    const float* __restrict__ gamma,
    const float* __restrict__ beta,
    const float* __restrict__ mean,
    const float* __restrict__ var,
    float* __restrict__ out)
{
    __shared__ __align__(16) float wS[GBK * WSTR];
    __shared__ __align__(16) float catS[256 * KSTR];
    const int t = threadIdx.x, lane = t & 31, wrp = t >> 5;
    const int ti = lane & 7, tjw = lane >> 3;
    const int r0 = blockIdx.x * 256, o0 = blockIdx.y * 64;

    unsigned long long acc[4][8];
#pragma unroll
    for (int p = 0; p < 4; p++)
#pragma unroll
        for (int nn = 0; nn < 8; nn++) acc[p][nn] = 0ULL;

    const int kq = t & 7, rowb = t >> 3;

    unsigned cb0 = (unsigned)__cvta_generic_to_shared(catS);
    unsigned cadr[8];
#pragma unroll
    for (int i = 0; i < 8; i++) {
        int n = wrp*32 + ((i < 4) ? (4*tjw + i) : (16 + 4*tjw + i - 4));
        cadr[i] = cb0 + (unsigned)(n * KSTR * 4);
    }

    float4 cv[8], wv[2];
#define LOADA(KC) do {                                                        \
        _Pragma("unroll")                                                     \
        for (int s = 0; s < 8; s++) {                                         \
            size_t ix = (size_t)(r0 + rowb + 32*s)*Cch + (KC) + kq*4;         \
            float4 h = *reinterpret_cast<const float4*>(&g_att[ix]);          \
            float4 w = *reinterpret_cast<const float4*>(&g_attw[ix]);         \
            cv[s] = make_float4(h.x+w.x, h.y+w.y, h.z+w.z, h.w+w.w);          \
        }                                                                     \
        _Pragma("unroll")                                                     \
        for (int s = 0; s < 2; s++)                                           \
            wv[s] = *reinterpret_cast<const float4*>(                         \
                &cw[(o0 + rowb + 32*s)*384 + 192 + (KC) + kq*4]);             \
    } while (0)

    LOADA(0);
#pragma unroll 1
    for (int it = 0; it < 6; it++) {
        __syncthreads();
#pragma unroll
        for (int s = 0; s < 8; s++) {
            const float* cp = &cv[s].x;
#pragma unroll
            for (int j = 0; j < 4; j++)
                catS[(rowb + 32*s)*KSTR + kq*4 + j] = cp[j];
        }
#pragma unroll
        for (int s = 0; s < 2; s++) {
            const float* wp = &wv[s].x;
#pragma unroll
            for (int j = 0; j < 4; j++)
                wS[(kq*4 + j)*WSTR + rowb + 32*s] = wp[j];
        }
        __syncthreads();
        if (it < 5) LOADA((it + 1) * GBK);
#pragma unroll 16
        for (int k = 0; k < GBK; k++) {
            ulonglong2 A0 = *reinterpret_cast<const ulonglong2*>(
                                &wS[k*WSTR + 4*ti]);
            ulonglong2 A1 = *reinterpret_cast<const ulonglong2*>(
                                &wS[k*WSTR + 32 + 4*ti]);
            unsigned long long a[4] = {A0.x, A0.y, A1.x, A1.y};
            unsigned long long bb[8];
#pragma unroll
            for (int i = 0; i < 8; i++)
                LDSDUP(bb[i], cadr[i] + (unsigned)(4*k));
#pragma unroll
            for (int p = 0; p < 4; p++)
#pragma unroll
                for (int nn = 0; nn < 8; nn++)
                    FFMA2(acc[p][nn], a[p], bb[nn]);
        }
    }

#pragma unroll
    for (int qd = 0; qd < 2; qd++) {
        const int rq = r0 + wrp*32 + qd*16 + 4*tjw;
        const int bq = rq / HW;
        const int nq = rq - bq*HW;
#pragma unroll
        for (int p = 0; p < 4; p++) {
            const int ob = (p < 2) ? (4*ti + 2*p) : (32 + 4*ti + 2*(p - 2));
#pragma unroll
            for (int q = 0; q < 2; q++) {
                const int o = o0 + ob + q;
                const float bi  = bias[o];
                const float inv = gamma[o] * rsqrtf(var[o] + 1e-5f);
                const float mu  = mean[o], bt = beta[o];
                float4 av = *reinterpret_cast<const float4*>(
                                &g_acc[(size_t)o*(Bsz*HW) + rq]);
                const float* ap = &av.x;
                float4 rv; float* rp = &rv.x;
#pragma unroll
                for (int ii = 0; ii < 4; ii++) {
                    unsigned long long v = acc[p][qd*4 + ii];
                    float yv = q ? __uint_as_float((unsigned)(v >> 32))
                                 : __uint_as_float((unsigned)v);
                    float y = (yv + ap[ii] + bi - mu) * inv + bt;
                    rp[ii] = 0.5f * y * (1.0f + erff(y * 0.70710678118654752f));
                }
                *reinterpret_cast<float4*>(
                    &out[(size_t)(bq*Cch + o)*HW + nq]) = rv;
            }
        }
    }
}

// ---------------------------------------------------------------------------
extern "C" void kernel_launch(void* const* d_in, const int* in_sizes, int n_in,
                              void* d_out, int out_size)
{
    const float* x     = (const float*)d_in[0];
    const float* cw    = (const float*)d_in[1];
    const float* cb    = (const float*)d_in[2];
    const float* gamma = (const float*)d_in[3];
    const float* beta  = (const float*)d_in[4];
    const float* mean  = (const float*)d_in[5];
    const float* var   = (const float*)d_in[6];
    float* out = (float*)d_out;

    static cudaStream_t s2 = nullptr, s3 = nullptr;
    static cudaEvent_t evA = nullptr, evB = nullptr, evC = nullptr;
    if (!s2) {
        cudaStreamCreateWithFlags(&s2, cudaStreamNonBlocking);
        cudaStreamCreateWithFlags(&s3, cudaStreamNonBlocking);
        cudaEventCreateWithFlags(&evA, cudaEventDisableTiming);
        cudaEventCreateWithFlags(&evB, cudaEventDisableTiming);
        cudaEventCreateWithFlags(&evC, cudaEventDisableTiming);
        cudaFuncSetAttribute(gemm_x,
            cudaFuncAttributeMaxDynamicSharedMemorySize, DSMB_X);
    }

    transpose_k<<<dim3(HW/32, Cch/32, Bsz), dim3(32, 8)>>>(x);

    // fork: score/sum launched FIRST (seed SMs), gemm_x forced 1 block/SM
    cudaEventRecord(evA, 0);
    cudaStreamWaitEvent(s3, evA, 0);
    cudaStreamWaitEvent(s2, evA, 0);

    score_k<<<dim3(56, 4, 2*Bsz), 192, 0, s3>>>();
    sum_k<<<dim3(56, 4, 2*Bsz), 192, 0, s3>>>();

    gemm_x<<<dim3(98, 3), 256, DSMB_X, s2>>>(cw);

    // join, then att-half GEMM + epilogue
    cudaEventRecord(evB, s2);
    cudaEventRecord(evC, s3);
    cudaStreamWaitEvent(0, evB, 0);
    cudaStreamWaitEvent(0, evC, 0);
    gemm_att<<<dim3(49, 3), 256>>>(cw, cb, gamma, beta, mean, var, out);
}

// round 16
// speedup vs baseline: 1.1343x; 1.0894x over previous
#include <cuda_runtime.h>
#include <math.h>

#define Bsz 4
#define Cch 192
#define Hh 56
#define Ww 56
#define HW (Hh*Ww)

// scratch (static device globals; no allocation)
__device__ float g_xt  [Bsz*HW*Cch];  // x transposed to [b][n][c]  (NHWC)
__device__ float g_att [Bsz*HW*Cch];  // attention output, h-shift part
__device__ float g_attw[Bsz*HW*Cch];  // attention output, w-shift part
__device__ __align__(16) float g_sc[Bsz*HW*32];  // scores, padded rows of 32

// ---------------------------------------------------------------------------
// Kernel 1: NCHW -> NHWC transpose
// ---------------------------------------------------------------------------
__global__ __launch_bounds__(256) void transpose_k(const float* __restrict__ x)
{
    __shared__ float tile[32][33];
    const int n0 = blockIdx.x << 5;
    const int c0 = blockIdx.y << 5;
    const int b  = blockIdx.z;
    const int tx = threadIdx.x, ty = threadIdx.y;
    const float* xb = x + (size_t)b * Cch * HW;
#pragma unroll
    for (int i = 0; i < 4; i++)
        tile[ty + i*8][tx] = xb[(size_t)(c0 + ty + i*8) * HW + n0 + tx];
    __syncthreads();
    float* dst = g_xt + (size_t)b * HW * Cch;
#pragma unroll
    for (int i = 0; i < 4; i++)
        dst[(size_t)(n0 + ty + i*8) * Cch + c0 + tx] = tile[tx][ty + i*8];
}

// ---------------------------------------------------------------------------
// tanh: (1-e)/(1+e) = 2*rcp(1+e) - 1,  e = 2^(-2a*log2e).  6 instr / 2 MUFU.
// ---------------------------------------------------------------------------
__device__ __forceinline__ float fast_tanh(float p)
{
    float z = fabsf(p) * -2.885390082f;
    float e; asm("ex2.approx.f32 %0, %1;" : "=f"(e) : "f"(z));
    float d = 1.0f + e;
    float r; asm("rcp.approx.f32 %0, %1;" : "=f"(r) : "f"(d));
    float t = fmaf(2.0f, r, -1.0f);
    return copysignf(t, p);
}

// ---------------------------------------------------------------------------
// Kernel 2: ring pair-score kernel (unchanged from the 83.0us best)
// ---------------------------------------------------------------------------
#define TS_STRIDE 193

template<int LO, int HI, int MODE>
__device__ __forceinline__ void score_compute(const float* sxr, const float* xr,
                                              float* ts, int c)
{
    int p = 0;
#pragma unroll
    for (int i = 0; i < 14; i++)
#pragma unroll
        for (int j = (MODE ? i + 1 : i); j < 14; j++) {
            if (p >= LO && p < HI)
                ts[(p - LO)*TS_STRIDE + c] = fast_tanh(sxr[i] * xr[j]);
            p++;
        }
}

__device__ __forceinline__ void reduce_rows(const float* ts, float* redS,
                                            int c, int nrows, int base)
{
    if (c < nrows) {
        const float* row = ts + c*TS_STRIDE;
        float s0=0.f, s1=0.f, s2=0.f, s3=0.f;
#pragma unroll 8
        for (int cc = 0; cc < 192; cc += 4) {
            s0 += row[cc]; s1 += row[cc+1]; s2 += row[cc+2]; s3 += row[cc+3];
        }
        redS[base + c] = (s0 + s1) + (s2 + s3);
    }
}

__global__ __launch_bounds__(192) void score_k()
{
    __shared__ float ts[53 * TS_STRIDE];
    __shared__ float redS[105];
    const int x = blockIdx.x;
    const int r = blockIdx.y;
    const int b = blockIdx.z >> 1, mode = blockIdx.z & 1;
    const int c = threadIdx.x;
    const float* base = g_xt + (size_t)b * HW * Cch;

    float xr[14], sxr[14];
#pragma unroll
    for (int a = 0; a < 14; a++) {
        int n = mode ? (x*Ww + r + 4*a) : ((r + 4*a)*Ww + x);
        xr[a]  = base[n*Cch + c];
        sxr[a] = xr[a] * 0.19245008972987526f;
    }
    const int NP = mode ? 91 : 105;

    if (mode == 0) score_compute<0,53,0>(sxr, xr, ts, c);
    else           score_compute<0,53,1>(sxr, xr, ts, c);
    __syncthreads();
    reduce_rows(ts, redS, c, 53, 0);
    __syncthreads();
    if (mode == 0) score_compute<53,105,0>(sxr, xr, ts, c);
    else           score_compute<53,91,1>(sxr, xr, ts, c);
    __syncthreads();
    reduce_rows(ts, redS, c, NP - 53, 53);
    __syncthreads();

    float* scb = g_sc + (size_t)b * HW * 32;
    if (mode == 0) {
        for (int e = c; e < 196; e += 192) {
            int a = e / 14, k = e % 14;
            int j = a - k; if (j < 0) j += 14;
            int lo = min(a, j), hi = max(a, j);
            int id = lo*14 - (lo*(lo-1))/2 + (hi - lo);
            int n = (r + 4*a)*Ww + x;
            scb[n*32 + k] = redS[id];
        }
    } else {
        for (int e = c; e < 182; e += 192) {
            int a = e / 13, m = e % 13 + 1;
            int j = a - m; if (j < 0) j += 14;
            int lo = min(a, j), hi = max(a, j);
            int id = lo*13 - (lo*(lo-1))/2 + (hi - lo - 1);
            int n = x*Ww + r + 4*a;
            scb[n*32 + 13 + m] = redS[id];
        }
    }
}

// ---------------------------------------------------------------------------
// Kernel 3: ring weighted-sum. Softmax rows loaded as 7x LDG.128 (was 27
// scalar LDG) to shorten the 14-thread critical path.
// ---------------------------------------------------------------------------
__global__ __launch_bounds__(192) void sum_k()
{
    __shared__ float wgt[14*14];
    const int x = blockIdx.x, r = blockIdx.y;
    const int b = blockIdx.z >> 1, mode = blockIdx.z & 1;
    const int c = threadIdx.x;
    const float* base = g_xt + (size_t)b * HW * Cch;
    float* attb = (mode ? g_attw : g_att) + (size_t)b * HW * Cch;
    const float* scb = g_sc + (size_t)b * HW * 32;

    if (c < 14) {
        int n = mode ? (x*Ww + r + 4*c) : ((r + 4*c)*Ww + x);
        const float4* srow4 = reinterpret_cast<const float4*>(scb + n*32);
        float4 v[7];
#pragma unroll
        for (int q = 0; q < 7; q++) v[q] = srow4[q];   // 28 values, use 27
        float s[27];
#pragma unroll
        for (int q = 0; q < 7; q++) {
            const float* vp = &v[q].x;
#pragma unroll
            for (int j = 0; j < 4; j++)
                if (q*4 + j < 27) s[q*4 + j] = vp[j];
        }
        float mx = -1e30f;
#pragma unroll
        for (int k = 0; k < 27; k++) mx = fmaxf(mx, s[k]);
        float tot = 0.f;
#pragma unroll
        for (int k = 0; k < 27; k++) { s[k] = __expf(s[k] - mx); tot += s[k]; }
        float inv = __fdividef(1.f, tot);
        if (mode == 0) {
#pragma unroll
            for (int k = 0; k < 14; k++) wgt[c*14 + k] = s[k] * inv;
        } else {
#pragma unroll
            for (int m = 1; m < 14; m++) wgt[c*14 + m-1] = s[13 + m] * inv;
        }
    }
    __syncthreads();

    float xr[14];
#pragma unroll
    for (int a = 0; a < 14; a++) {
        int n = mode ? (x*Ww + r + 4*a) : ((r + 4*a)*Ww + x);
        xr[a] = base[n*Cch + c];
    }
#pragma unroll
    for (int a = 0; a < 14; a++) {
        int n = mode ? (x*Ww + r + 4*a) : ((r + 4*a)*Ww + x);
        float o = 0.f;
        if (mode == 0) {
#pragma unroll
            for (int k = 0; k < 14; k++) {
                int j = (a - k + 14) % 14;
                o = fmaf(wgt[a*14 + k], xr[j], o);
            }
        } else {
#pragma unroll
            for (int m = 1; m < 14; m++) {
                int j = (a - m + 14) % 14;
                o = fmaf(wgt[a*14 + m-1], xr[j], o);
            }
        }
        attb[n*Cch + c] = o;
    }
}

// ---------------------------------------------------------------------------
// Kernel 4: FFMA2 GEMM — byte-identical R7 design (validated 47.4us).
// M=192 x N=12544 x K=384 (+bias+BN+GELU), 8x8 thread tile, f32x2 accs.
// Block 64o x 256n, 256 thr, grid 49x3 = 147 (1/SM).
// ---------------------------------------------------------------------------
#define GBK 32
#define WSTR 68
#define KSTR 33

#define FFMA2(d, a, b) asm("fma.rn.f32x2 %0, %1, %2, %0;" : "+l"(d) : "l"(a), "l"(b))
#define LDSDUP(bb, addr)                                                      \
    asm volatile("{\n\t.reg .f32 t;\n\tld.shared.f32 t, [%1];\n\t"            \
                 "mov.b64 %0, {t, t};\n\t}" : "=l"(bb) : "r"(addr))

__global__ __launch_bounds__(256, 1) void gemm_k(
    const float* __restrict__ cw,
    const float* __restrict__ bias,
    const float* __restrict__ gamma,
    const float* __restrict__ beta,
    const float* __restrict__ mean,
    const float* __restrict__ var,
    float* __restrict__ out)
{
    __shared__ __align__(16) float wS[GBK * WSTR];    // 8.7KB
    __shared__ __align__(16) float catS[256 * KSTR];  // 33.8KB
    const int t  = threadIdx.x;
    const int lane = t & 31, wrp = t >> 5;
    const int ti = lane & 7, tjw = lane >> 3;   // 8 o-thr x 4 n-thr per warp
    const int o0 = blockIdx.y * 64;
    const int r0 = blockIdx.x * 256;

    unsigned long long acc[4][8];               // [o-pair][n]
#pragma unroll
    for (int p = 0; p < 4; p++)
#pragma unroll
        for (int nn = 0; nn < 8; nn++) acc[p][nn] = 0ULL;

    const int kq = t & 7, rowb = t >> 3;

    unsigned cb0 = (unsigned)__cvta_generic_to_shared(catS);
    unsigned cadr[8];
#pragma unroll
    for (int i = 0; i < 8; i++) {
        int n = wrp*32 + ((i < 4) ? (4*tjw + i) : (16 + 4*tjw + i - 4));
        cadr[i] = cb0 + (unsigned)(n * KSTR * 4);
    }

    float4 cv[8], wv[2];
#define LOAD_TILE(KC) do {                                                    \
        if ((KC) < Cch) {                                                     \
            _Pragma("unroll")                                                 \
            for (int s = 0; s < 8; s++)                                       \
                cv[s] = *reinterpret_cast<const float4*>(                     \
                    &g_xt[(size_t)(r0 + rowb + 32*s)*Cch + (KC) + kq*4]);     \
        } else {                                                              \
            _Pragma("unroll")                                                 \
            for (int s = 0; s < 8; s++) {                                     \
                size_t ix = (size_t)(r0 + rowb + 32*s)*Cch + (KC) - Cch + kq*4;\
                float4 h = *reinterpret_cast<const float4*>(&g_att[ix]);      \
                float4 w = *reinterpret_cast<const float4*>(&g_attw[ix]);     \
                cv[s] = make_float4(h.x+w.x, h.y+w.y, h.z+w.z, h.w+w.w);      \
            }                                                                 \
        }                                                                     \
        _Pragma("unroll")                                                     \
        for (int s = 0; s < 2; s++)                                           \
            wv[s] = *reinterpret_cast<const float4*>(                         \
                &cw[(o0 + rowb + 32*s)*384 + (KC) + kq*4]);                   \
    } while (0)

    LOAD_TILE(0);
#pragma unroll 1
    for (int it = 0; it < 12; it++) {
        __syncthreads();
#pragma unroll
        for (int s = 0; s < 8; s++) {
            const float* cp = &cv[s].x;
#pragma unroll
            for (int j = 0; j < 4; j++)
                catS[(rowb + 32*s)*KSTR + kq*4 + j] = cp[j];
        }
#pragma unroll
        for (int s = 0; s < 2; s++) {
            const float* wp = &wv[s].x;
#pragma unroll
            for (int j = 0; j < 4; j++)
                wS[(kq*4 + j)*WSTR + rowb + 32*s] = wp[j];
        }
        __syncthreads();
        if (it < 11) LOAD_TILE((it + 1) * GBK);
#pragma unroll 16
        for (int k = 0; k < GBK; k++) {
            ulonglong2 A0 = *reinterpret_cast<const ulonglong2*>(
                                &wS[k*WSTR + 4*ti]);
            ulonglong2 A1 = *reinterpret_cast<const ulonglong2*>(
                                &wS[k*WSTR + 32 + 4*ti]);
            unsigned long long a[4] = {A0.x, A0.y, A1.x, A1.y};
            unsigned long long bb[8];
#pragma unroll
            for (int i = 0; i < 8; i++)
                LDSDUP(bb[i], cadr[i] + (unsigned)(4*k));
#pragma unroll
            for (int p = 0; p < 4; p++)
#pragma unroll
                for (int nn = 0; nn < 8; nn++)
                    FFMA2(acc[p][nn], a[p], bb[nn]);
        }
    }

    // epilogue: bias + BN(eval) + exact GELU; per quad of 4 consecutive n
#pragma unroll
    for (int qd = 0; qd < 2; qd++) {
        const int rq = r0 + wrp*32 + qd*16 + 4*tjw;
        const int bq = rq / HW;                 // quad never splits batch
        const int nq = rq - bq*HW;
#pragma unroll
        for (int p = 0; p < 4; p++) {
            const int ob = (p < 2) ? (4*ti + 2*p) : (32 + 4*ti + 2*(p - 2));
#pragma unroll
            for (int q = 0; q < 2; q++) {
                const int o = o0 + ob + q;
                const float bi  = bias[o];
                const float inv = gamma[o] * rsqrtf(var[o] + 1e-5f);
                const float mu  = mean[o], bt = beta[o];
                float4 rv; float* rp = &rv.x;
#pragma unroll
                for (int ii = 0; ii < 4; ii++) {
                    unsigned long long v = acc[p][qd*4 + ii];
                    float yv = q ? __uint_as_float((unsigned)(v >> 32))
                                 : __uint_as_float((unsigned)v);
                    float y = (yv + bi - mu) * inv + bt;
                    rp[ii] = 0.5f * y * (1.0f + erff(y * 0.70710678118654752f));
                }
                *reinterpret_cast<float4*>(
                    &out[(size_t)(bq*Cch + o)*HW + nq]) = rv;
            }
        }
    }
}

// ---------------------------------------------------------------------------
extern "C" void kernel_launch(void* const* d_in, const int* in_sizes, int n_in,
                              void* d_out, int out_size)
{
    const float* x     = (const float*)d_in[0];
    const float* cw    = (const float*)d_in[1];
    const float* cb    = (const float*)d_in[2];
    const float* gamma = (const float*)d_in[3];
    const float* beta  = (const float*)d_in[4];
    const float* mean  = (const float*)d_in[5];
    const float* var   = (const float*)d_in[6];
    float* out = (float*)d_out;

    transpose_k<<<dim3(HW/32, Cch/32, Bsz), dim3(32, 8)>>>(x);
    score_k<<<dim3(56, 4, 2*Bsz), 192>>>();
    sum_k<<<dim3(56, 4, 2*Bsz), 192>>>();
    gemm_k<<<dim3(49, 3), 256>>>(cw, cb, gamma, beta, mean, var, out);
}